// round 16
// baseline (speedup 1.0000x reference)
#include <cuda_runtime.h>
#include <cuda_fp16.h>
#include <cstdint>

// ---------------- problem constants ----------------
#define KTOT   3072
#define NOUT   12288
#define MB     64             // batch (GEMM N side)
#define MTILE  32             // output rows per CTA
#define KC     64             // K per chunk
#define NCHUNK (KTOT / KC)    // 48
#define NTH    256
#define NCTA   (NOUT / MTILE) // 384

// ---- smem layout ----
// A packed : 2 x (32 rows x 64B int8, XOR-word layout) at 0
// scales   : 3 x 256B (cp.async stages)                at 4096
// bias     : 128B at 9216 (epilogue transpose uses [0, 9216))
#define SM_APK(b) ((uint32_t)(b) * 2048u)
#define SM_S(s)   (4096u + (uint32_t)(s) * 256u)
#define SM_BIAS   9216u
#define SMEM_TOTAL 9472u
#define EPI_RSTRIDE 36        // floats per epi row (144B, 16B-aligned)

// x pre-converted to fp16 (plain k-major [64][3072], NO permutation)
__device__ __align__(16) __half g_xh[MB * KTOT];

__global__ void xconv_kernel(const float* __restrict__ x) {
    int i = blockIdx.x * blockDim.x + threadIdx.x;   // float4 index
    float4 v = ((const float4*)x)[i];
    __half2 h0 = __floats2half2_rn(v.x, v.y);
    __half2 h1 = __floats2half2_rn(v.z, v.w);
    uint2 r;
    r.x = *reinterpret_cast<uint32_t*>(&h0);
    r.y = *reinterpret_cast<uint32_t*>(&h1);
    ((uint2*)g_xh)[i] = r;
}

// ---------------- device helpers ----------------
__device__ __forceinline__ uint32_t smem_u32(const void* p) {
    uint32_t a;
    asm("{ .reg .u64 t; cvta.to.shared.u64 t, %1; cvt.u32.u64 %0, t; }" : "=r"(a) : "l"(p));
    return a;
}
__device__ __forceinline__ void cp_async8(uint32_t dst, const void* src) {
    asm volatile("cp.async.ca.shared.global [%0], [%1], 8;"
                 :: "r"(dst), "l"(src) : "memory");
}
#define CP_COMMIT()  asm volatile("cp.async.commit_group;" ::: "memory")
#define CP_WAIT(n)   asm volatile("cp.async.wait_group %0;" :: "n"(n) : "memory")

__device__ __forceinline__ void sts32(uint32_t addr, uint32_t v) {
    asm volatile("st.shared.b32 [%0], %1;" :: "r"(addr), "r"(v) : "memory");
}
__device__ __forceinline__ uint32_t lds32(uint32_t addr) {
    uint32_t v;
    asm volatile("ld.shared.b32 %0, [%1];" : "=r"(v) : "r"(addr));
    return v;
}
__device__ __forceinline__ void mma16816(float* c,
                                         uint32_t a0, uint32_t a1, uint32_t a2, uint32_t a3,
                                         uint32_t b0, uint32_t b1) {
    asm volatile(
        "mma.sync.aligned.m16n8k16.row.col.f32.f16.f16.f32 "
        "{%0,%1,%2,%3}, {%4,%5,%6,%7}, {%8,%9}, {%0,%1,%2,%3};"
        : "+f"(c[0]), "+f"(c[1]), "+f"(c[2]), "+f"(c[3])
        : "r"(a0), "r"(a1), "r"(a2), "r"(a3), "r"(b0), "r"(b1));
}
__device__ __forceinline__ uint32_t pack4(int4 c) {   // low bytes of 4 codes
    uint32_t u = __byte_perm((uint32_t)c.x, (uint32_t)c.y, 0x0040);
    uint32_t v = __byte_perm((uint32_t)c.z, (uint32_t)c.w, 0x0040);
    return __byte_perm(u, v, 0x5410);
}
__device__ __forceinline__ uint32_t dq_h(uint32_t packed, uint32_t sel, __half2 s2) {
    const __half2 c1152 = __half2(__ushort_as_half((unsigned short)0x6480),
                                  __ushort_as_half((unsigned short)0x6480));
    uint32_t h = __byte_perm(packed, 0x64006400u, sel);
    __half2 v = __hmul2(__hsub2(*(__half2*)&h, c1152), s2);
    return *(uint32_t*)&v;
}

__global__ __launch_bounds__(NTH, 3)
void dql_kernel(const int*   __restrict__ wq,
                const float* __restrict__ ws,
                const int*   __restrict__ bq,
                const float* __restrict__ bs,
                float*       __restrict__ out) {
    extern __shared__ __align__(16) char smem[];
    const uint32_t sb = smem_u32(smem);
    float* smf = (float*)smem;

    const int tid  = threadIdx.x;
    const int lane = tid & 31;
    const int wn   = tid >> 5;     // warp owns batch slice n8: rows wn*8..+8
    const int cta  = blockIdx.x;

    if (tid < MTILE) {
        const int o = cta * MTILE + tid;
        ((float*)(smem + SM_BIAS))[tid] = ((float)bq[o] - 128.0f) * bs[o >> 5];
    }

    // ---- A producer: LDG raw codes, pack to int8, STS (XOR word layout) ----
    const int a_R = tid >> 3;      // 0..31 (weight row)
    const int a_s = tid & 7;       // word (4-code) segment; covers a_s, a_s+8
    const int* a_src = wq + (size_t)(cta * MTILE + a_R) * KTOT + a_s * 4;
    const uint32_t a_pv = (uint32_t)(((a_R >> 1) & 3) << 2);
    const uint32_t a_d0 = (uint32_t)(a_R * 64) + ((((uint32_t)a_s)       ^ a_pv) << 2);
    const uint32_t a_d1 = (uint32_t)(a_R * 64) + ((((uint32_t)(a_s + 8)) ^ a_pv) << 2);

    // ---- scales cp.async (3 stages) ----
    const float* s_src0 = ws + (size_t)(cta * MTILE + tid) * (KTOT / 32);
    auto issueS = [&](int c) {
        if (tid < MTILE)
            cp_async8(sb + SM_S(c % 3) + (uint32_t)(tid * 8), s_src0 + c * 2);
    };

    int4 ar0, ar1;                 // A LDG staging (one chunk)
    auto ldgA = [&](int c) {
        const int* p = a_src + c * KC;
        ar0 = *(const int4*)(p);
        ar1 = *(const int4*)(p + 32);
    };
    auto stsA = [&](int c) {
        const uint32_t base = sb + SM_APK(c & 1);
        sts32(base + a_d0, pack4(ar0));
        sts32(base + a_d1, pack4(ar1));
    };

    // ---- B direct-from-gmem fragments ----
    const int g   = lane >> 2;     // row group 0..7
    const int tig = lane & 3;      // k sub-lane
    const __half* b_ptr = g_xh + (size_t)(wn * 8 + g) * KTOT + 4 * tig;
    uint2 bcur[4], bnxt[4];
    auto ldgB = [&](int c, uint2* dst) {
#pragma unroll
        for (int t = 0; t < 4; t++)
            dst[t] = *(const uint2*)(b_ptr + c * KC + t * 16);
    };

    float acc[2][4];
#pragma unroll
    for (int u = 0; u < 2; u++)
#pragma unroll
        for (int i = 0; i < 4; i++) acc[u][i] = 0.0f;

    // ---- consumer addressing ----
    const uint32_t c_pv = (uint32_t)(((g >> 1) & 3) << 2);   // same for g+8j
    const uint32_t rb0 = (uint32_t)(g * 64);
    const uint32_t rb1 = (uint32_t)((g + 8) * 64);
    const uint32_t rb2 = (uint32_t)((g + 16) * 64);
    const uint32_t rb3 = (uint32_t)((g + 24) * 64);

    // ---- prologue ----
    issueS(0); CP_COMMIT();
    issueS(1); CP_COMMIT();
    ldgA(0); stsA(0);
    ldgA(1);
    ldgB(0, bcur);

    for (int c = 0; c < NCHUNK; c++) {
        CP_WAIT(1);                  // scales stage c complete
        __syncthreads();             // APK[c&1] visible; slot reuse safe

        issueS(c + 2 < NCHUNK ? c + 2 : c);   // keep group arithmetic (re-issue is harmless)
        CP_COMMIT();
        if (c + 1 < NCHUNK) {
            stsA(c + 1);
            ldgB(c + 1, bnxt);
        }
        if (c + 2 < NCHUNK) ldgA(c + 2);

        // per-row scale half2s for this chunk (blocks 2c, 2c+1)
        const uint32_t Ss = SM_S(c % 3);
        __half2 sh[4][2];
#pragma unroll
        for (int j = 0; j < 4; j++) {
            float2 s = *(const float2*)(smem + Ss + (uint32_t)((g + 8 * j) * 8));
            sh[j][0] = __float2half2_rn(s.x);
            sh[j][1] = __float2half2_rn(s.y);
        }

        const uint32_t APK = sb + SM_APK(c & 1);
#pragma unroll
        for (int t = 0; t < 4; t++) {
            const uint32_t woff = ((((uint32_t)(t * 4 + tig)) ^ c_pv) << 2);
            const int blk = t >> 1;
            uint32_t p0 = lds32(APK + rb0 + woff);
            uint32_t p1 = lds32(APK + rb1 + woff);
            uint32_t p2 = lds32(APK + rb2 + woff);
            uint32_t p3 = lds32(APK + rb3 + woff);

            // m-frag 0: rows g, g+8
            {
                uint32_t a0 = dq_h(p0, 0x5150, sh[0][blk]);
                uint32_t a1 = dq_h(p1, 0x5150, sh[1][blk]);
                uint32_t a2 = dq_h(p0, 0x5352, sh[0][blk]);
                uint32_t a3 = dq_h(p1, 0x5352, sh[1][blk]);
                mma16816(acc[0], a0, a1, a2, a3, bcur[t].x, bcur[t].y);
            }
            // m-frag 1: rows g+16, g+24
            {
                uint32_t a0 = dq_h(p2, 0x5150, sh[2][blk]);
                uint32_t a1 = dq_h(p3, 0x5150, sh[3][blk]);
                uint32_t a2 = dq_h(p2, 0x5352, sh[2][blk]);
                uint32_t a3 = dq_h(p3, 0x5352, sh[3][blk]);
                mma16816(acc[1], a0, a1, a2, a3, bcur[t].x, bcur[t].y);
            }
        }
#pragma unroll
        for (int t = 0; t < 4; t++) bcur[t] = bnxt[t];
    }

    // ---- epilogue: smem transpose + bias + coalesced stores ----
    __syncthreads();
    {
        // C frag: c0=C[g][nb], c1=C[g][nb+1], c2=C[g+8][nb], c3=C[g+8][nb+1]
        const int nb = wn * 8 + tig * 2;           // batch column
#pragma unroll
        for (int u = 0; u < 2; u++) {
            const int orow = u * 16 + g;
            smf[nb * EPI_RSTRIDE + orow]           = acc[u][0];
            smf[(nb + 1) * EPI_RSTRIDE + orow]     = acc[u][1];
            smf[nb * EPI_RSTRIDE + orow + 8]       = acc[u][2];
            smf[(nb + 1) * EPI_RSTRIDE + orow + 8] = acc[u][3];
        }
    }
    __syncthreads();
    {
        const int m  = tid >> 2;      // batch row 0..63
        const int qq = tid & 3;       // 8-float segment
        const float* row  = smf + m * EPI_RSTRIDE + qq * 8;
        const float* bias = (const float*)(smem + SM_BIAS) + qq * 8;
        float* op = out + (size_t)m * NOUT + cta * MTILE + qq * 8;
        float4 v0 = *(const float4*)(row);
        float4 v1 = *(const float4*)(row + 4);
        float4 b0 = *(const float4*)(bias);
        float4 b1 = *(const float4*)(bias + 4);
        v0.x += b0.x; v0.y += b0.y; v0.z += b0.z; v0.w += b0.w;
        v1.x += b1.x; v1.y += b1.y; v1.z += b1.z; v1.w += b1.w;
        *(float4*)(op)     = v0;
        *(float4*)(op + 4) = v1;
    }
}

extern "C" void kernel_launch(void* const* d_in, const int* in_sizes, int n_in,
                              void* d_out, int out_size) {
    (void)in_sizes; (void)n_in; (void)out_size;
    xconv_kernel<<<(MB * KTOT / 4) / NTH, NTH>>>((const float*)d_in[0]);
    cudaFuncSetAttribute(dql_kernel, cudaFuncAttributeMaxDynamicSharedMemorySize, SMEM_TOTAL);
    dql_kernel<<<NCTA, NTH, SMEM_TOTAL>>>(
        (const int*)d_in[1],     // w_q
        (const float*)d_in[2],   // w_scales
        (const int*)d_in[3],     // b_q
        (const float*)d_in[4],   // b_scales
        (float*)d_out);
}

// round 17
// speedup vs baseline: 1.0078x; 1.0078x over previous
#include <cuda_runtime.h>
#include <cuda_fp16.h>
#include <cstdint>

// ---------------- problem constants ----------------
#define KTOT   3072
#define NOUT   12288
#define MB     64             // batch (GEMM N side)
#define MTILE  32             // output rows per CTA
#define KC     64             // K per chunk
#define NCHUNK (KTOT / KC)    // 48
#define NTH    256
#define NCTA   (NOUT / MTILE) // 384

// ---- stage layout (4 stages) ----
// A codes : 32 rows x 256 B (int32, XOR-swizzled int2 positions) at +0
// scales  : 32 rows x float2                                      at +8192
#define ST_STRIDE 8448u
#define SM_S_OFF  8192u
#define SM_BIAS   33792u      // 4*ST_STRIDE ; epilogue transpose uses [0,33792)
#define SMEM_TOTAL 33920u
#define EPI_RSTRIDE 33        // floats per row in epilogue warp region

// x pre-converted to fp16 (plain k-major [64][3072])
__device__ __align__(16) __half g_xh[MB * KTOT];

__global__ void xconv_kernel(const float* __restrict__ x) {
    int i = blockIdx.x * blockDim.x + threadIdx.x;   // float4 index
    float4 v = ((const float4*)x)[i];
    __half2 h0 = __floats2half2_rn(v.x, v.y);
    __half2 h1 = __floats2half2_rn(v.z, v.w);
    uint2 r;
    r.x = *reinterpret_cast<uint32_t*>(&h0);
    r.y = *reinterpret_cast<uint32_t*>(&h1);
    ((uint2*)g_xh)[i] = r;
}

// ---------------- device helpers ----------------
__device__ __forceinline__ uint32_t smem_u32(const void* p) {
    uint32_t a;
    asm("{ .reg .u64 t; cvta.to.shared.u64 t, %1; cvt.u32.u64 %0, t; }" : "=r"(a) : "l"(p));
    return a;
}
__device__ __forceinline__ void cp_async16(uint32_t dst, const void* src) {
    asm volatile("cp.async.cg.shared.global [%0], [%1], 16;"
                 :: "r"(dst), "l"(src) : "memory");
}
__device__ __forceinline__ void cp_async8(uint32_t dst, const void* src) {
    asm volatile("cp.async.ca.shared.global [%0], [%1], 8;"
                 :: "r"(dst), "l"(src) : "memory");
}
#define CP_COMMIT()  asm volatile("cp.async.commit_group;" ::: "memory")
#define CP_WAIT(n)   asm volatile("cp.async.wait_group %0;" :: "n"(n) : "memory")

__device__ __forceinline__ void lds64(uint32_t& x, uint32_t& y, uint32_t addr) {
    asm volatile("ld.shared.v2.b32 {%0,%1}, [%2];" : "=r"(x), "=r"(y) : "r"(addr));
}
__device__ __forceinline__ uint32_t ldg32(const void* p) {
    uint32_t v;
    asm volatile("ld.global.nc.b32 %0, [%1];" : "=r"(v) : "l"(p));
    return v;
}
__device__ __forceinline__ void mma16816(float* c,
                                         uint32_t a0, uint32_t a1, uint32_t a2, uint32_t a3,
                                         uint32_t b0, uint32_t b1) {
    asm volatile(
        "mma.sync.aligned.m16n8k16.row.col.f32.f16.f16.f32 "
        "{%0,%1,%2,%3}, {%4,%5,%6,%7}, {%8,%9}, {%0,%1,%2,%3};"
        : "+f"(c[0]), "+f"(c[1]), "+f"(c[2]), "+f"(c[3])
        : "r"(a0), "r"(a1), "r"(a2), "r"(a3), "r"(b0), "r"(b1));
}

__global__ __launch_bounds__(NTH, 3)
void dql_kernel(const int*   __restrict__ wq,
                const float* __restrict__ ws,
                const int*   __restrict__ bq,
                const float* __restrict__ bs,
                float*       __restrict__ out) {
    extern __shared__ __align__(16) char smem[];
    const uint32_t sb = smem_u32(smem);
    float* smf = (float*)smem;

    const int tid  = threadIdx.x;
    const int lane = tid & 31;
    const int wid  = tid >> 5;
    const int wk   = wid >> 1;     // k-split quarter (16 k per warp per chunk)
    const int wn   = wid & 1;      // batch half (32)
    const int cta  = blockIdx.x;

    if (tid < MTILE) {
        const int o = cta * MTILE + tid;
        ((float*)(smem + SM_BIAS))[tid] = ((float)bq[o] - 128.0f) * bs[o >> 5];
    }

    // ---- A cp.async producer (raw int32 codes, XOR-int2 swizzle) ----
    const int a_R = tid >> 3;                 // 0..31 (weight row)
    const int a_s = tid & 7;                  // 16B segment (covers a_s, a_s+8)
    const char* a_src0 = (const char*)(wq + (size_t)(cta * MTILE + a_R) * KTOT) + a_s * 16;
    const uint32_t a_e  = (uint32_t)((a_R & 7) << 2);
    const uint32_t a_d0 = (uint32_t)(a_R * 256) + (((uint32_t)(2 * a_s)      ^ a_e) * 8);
    const uint32_t a_d1 = (uint32_t)(a_R * 256) + (((uint32_t)(2 * a_s + 16) ^ a_e) * 8);
    const char* s_src0 = (const char*)(ws + (size_t)(cta * MTILE + tid) * (KTOT / 32));

    auto issueStage = [&](int c) {
        const uint32_t st = sb + (uint32_t)(c & 3) * ST_STRIDE;
        const char* s = a_src0 + (size_t)c * 256;
        cp_async16(st + a_d0, s);
        cp_async16(st + a_d1, s + 128);
        if (tid < MTILE)
            cp_async8(st + SM_S_OFF + (uint32_t)(tid * 8), s_src0 + (size_t)c * 8);
    };

    float acc[2][4][4];
#pragma unroll
    for (int mf = 0; mf < 2; mf++)
#pragma unroll
        for (int nf = 0; nf < 4; nf++)
#pragma unroll
            for (int i = 0; i < 4; i++) acc[mf][nf][i] = 0.0f;

    // ---- consumer addressing ----
    const int r      = lane >> 2;                  // fragment base row
    const int tig    = lane & 3;
    const int k2base = wk * 8 + tig;               // int2 index within 32
    const int kb4    = (wk >> 1) * 4;              // scale word sel within float2
    const __half2 c1152 = __half2(__ushort_as_half((unsigned short)0x6480),
                                  __ushort_as_half((unsigned short)0x6480));

    // ---- B direct-from-L2 fragment pointers ----
    // frag nf: n = wn*32 + nf*8 + (lane>>2); reg0 at k = wk*16 + 2*tig; reg1 at +8
    const __half* b_base = g_xh + (size_t)(wn * 32 + r) * KTOT + wk * 16 + 2 * tig;
    uint32_t bcur[4][2], bnxt[4][2];
    auto ldgB = [&](int c, uint32_t d[4][2]) {
        const __half* p = b_base + c * KC;
#pragma unroll
        for (int nf = 0; nf < 4; nf++) {
            d[nf][0] = ldg32(p + (size_t)(nf * 8) * KTOT);
            d[nf][1] = ldg32(p + (size_t)(nf * 8) * KTOT + 8);
        }
    };

    // ---- prologue: 3 A stages in flight, B chunk 0 in regs ----
    issueStage(0); CP_COMMIT();
    issueStage(1); CP_COMMIT();
    issueStage(2); CP_COMMIT();
    ldgB(0, bcur);

    for (int c = 0; c < NCHUNK; c++) {
        CP_WAIT(2);                  // stage c complete
        __syncthreads();             // visibility; slot (c+3)&3 safe to overwrite

        if (c + 3 < NCHUNK) issueStage(c + 3);
        CP_COMMIT();
        if (c + 1 < NCHUNK) ldgB(c + 1, bnxt);

        const uint32_t stOff = (uint32_t)(c & 3) * ST_STRIDE;
        const uint32_t As = sb + stOff;
        const uint32_t Ss = sb + stOff + SM_S_OFF;

        // ---- dequant codes -> A fragments in registers (k-split, no dup) ----
        uint32_t a[2][4];
#pragma unroll
        for (int j = 0; j < 4; j++) {
            const int R = r + 8 * j;
            float s;
            asm volatile("ld.shared.f32 %0, [%1];" : "=f"(s)
                         : "r"(Ss + (uint32_t)(R * 8 + kb4)));
            const __half2 s2 = __float2half2_rn(s);
            const uint32_t rowb = As + (uint32_t)(R * 256);
            const uint32_t e    = (uint32_t)((R & 7) << 2);
#pragma unroll
            for (int h = 0; h < 2; h++) {
                const uint32_t k2 = (uint32_t)(k2base + 4 * h);
                uint32_t cx, cy;
                lds64(cx, cy, rowb + ((k2 ^ e) * 8));
                uint32_t v = __byte_perm(cx, cy, 0x3430) | 0x64006400u;
                __half2 hv = __hmul2(__hsub2(*(__half2*)&v, c1152), s2);
                a[j >> 1][(j & 1) + 2 * h] = *(uint32_t*)&hv;
            }
        }

        // ---- mma with register B fragments ----
#pragma unroll
        for (int mf = 0; mf < 2; mf++)
#pragma unroll
            for (int nf = 0; nf < 4; nf++)
                mma16816(acc[mf][nf], a[mf][0], a[mf][1], a[mf][2], a[mf][3],
                         bcur[nf][0], bcur[nf][1]);

#pragma unroll
        for (int nf = 0; nf < 4; nf++) {
            bcur[nf][0] = bnxt[nf][0];
            bcur[nf][1] = bnxt[nf][1];
        }
    }

    // ---- epilogue: per-warp partials -> smem, reduce over wk, bias, store ----
    __syncthreads();
    {
        const uint32_t wbase = (uint32_t)(wid * 32 * EPI_RSTRIDE);
        const int g = lane >> 2;
        const int q = (lane & 3) * 2;
#pragma unroll
        for (int mf = 0; mf < 2; mf++)
#pragma unroll
            for (int nf = 0; nf < 4; nf++) {
                const int row = mf * 16 + g;
                const int col = nf * 8 + q;
                smf[wbase + row * EPI_RSTRIDE + col]            = acc[mf][nf][0];
                smf[wbase + row * EPI_RSTRIDE + col + 1]        = acc[mf][nf][1];
                smf[wbase + (row + 8) * EPI_RSTRIDE + col]      = acc[mf][nf][2];
                smf[wbase + (row + 8) * EPI_RSTRIDE + col + 1]  = acc[mf][nf][3];
            }
    }
    __syncthreads();
    {
        const int row = tid & 31;
        const int mg  = tid >> 5;
        const float bias = ((const float*)(smem + SM_BIAS))[row];
        float* op = out + (size_t)cta * MTILE + row;
#pragma unroll
        for (int j = 0; j < 8; j++) {
            const int m   = mg * 8 + j;
            const int wn_ = m >> 5;
            const int ml  = m & 31;
            float v = bias;
#pragma unroll
            for (int k4 = 0; k4 < 4; k4++)
                v += smf[(uint32_t)((k4 * 2 + wn_) * 32 * EPI_RSTRIDE + row * EPI_RSTRIDE + ml)];
            op[(size_t)m * NOUT] = v;
        }
    }
}

extern "C" void kernel_launch(void* const* d_in, const int* in_sizes, int n_in,
                              void* d_out, int out_size) {
    (void)in_sizes; (void)n_in; (void)out_size;
    xconv_kernel<<<(MB * KTOT / 4) / NTH, NTH>>>((const float*)d_in[0]);
    cudaFuncSetAttribute(dql_kernel, cudaFuncAttributeMaxDynamicSharedMemorySize, SMEM_TOTAL);
    dql_kernel<<<NCTA, NTH, SMEM_TOTAL>>>(
        (const int*)d_in[1],     // w_q
        (const float*)d_in[2],   // w_scales
        (const int*)d_in[3],     // b_q
        (const float*)d_in[4],   // b_scales
        (float*)d_out);
}